// round 9
// baseline (speedup 1.0000x reference)
#include <cuda_runtime.h>
#include <math.h>

#define BSZ 8
#define NA 3
#define HH 76
#define WW 76
#define WH (HH*WW)            // 5776
#define NC 80
#define TT 50
#define CPB 512               // cells per block
#define NBY ((WH + CPB - 1)/CPB)   // 12
#define NBLK (BSZ*NA*NBY)     // 288

// persistent device scratch (rewritten every run)
__device__ float g_part[3*NBLK];
__device__ int   g_count = 0;

// anchors / stride(=8)
__constant__ float c_aw[9] = {17.75f, 24.f, 57.375f, 4.5f, 9.5f, 9.f,   1.5f, 2.375f, 5.f};
__constant__ float c_ah[9] = {13.75f, 30.375f, 50.125f, 9.375f, 6.875f, 18.25f, 2.f, 4.5f, 3.5f};

__device__ __forceinline__ float sigmoidf_(float x) { return 1.f/(1.f+__expf(-x)); }
// bce(sigmoid(x),1)=softplus(-x), bce(sigmoid(x),0)=softplus(x); fast MUFU version
__device__ __forceinline__ float softplusf_(float x) {
    return fmaxf(x, 0.f) + __logf(1.f + __expf(-fabsf(x)));
}

__global__ __launch_bounds__(CPB) void yolo_fused(const float* __restrict__ in,
                                                  const float* __restrict__ tb,
                                                  const int*   __restrict__ tc,
                                                  float* __restrict__ out)
{
    const int ba = blockIdx.x;                 // 0..23
    const int b  = ba / NA, a = ba % NA;
    const int lo = blockIdx.y * CPB;
    const int tidx = threadIdx.x;
    const int cell0 = lo + tidx;
    const bool live = cell0 < WH;
    const int cell = live ? cell0 : 0;

    __shared__ float4   s_gb[TT];      // sorted corner boxes
    __shared__ float    s_ag[TT];      // sorted gt area/3 (ascending)
    __shared__ float    s_key[TT];
    __shared__ float4   s_tbox[TT];    // unsorted (gx,gy,gw,gh)
    __shared__ float    s_scale[TT];   // unsorted 2 - sx*sy
    __shared__ int      s_map[CPB];
    __shared__ unsigned s_cb[3][CPB];

    // ---- hoisted input loads (latency overlaps target prep + barriers) ----
    const float* base = in + (size_t)ba*(5+NC)*WH + cell;
    float t0 = __ldg(base);
    float t1 = __ldg(base + WH);
    float t2 = __ldg(base + 2*WH);
    float t3 = __ldg(base + 3*WH);
    float t4 = __ldg(base + 4*WH);

    // ---- phase A: init + per-target prep ----
    s_map[tidx] = -1;
    s_cb[0][tidx] = 0u; s_cb[1][tidx] = 0u; s_cb[2][tidx] = 0u;

    float key = 0.f; float4 gb4; int cellt = -1, aprime = -1, cls = 0;
    if (tidx < TT) {
        const float* p = tb + (size_t)(b*TT + tidx)*4;
        float gx = p[0]*(float)WW, gy = p[1]*(float)HH;
        float gw = p[2]*(float)WW, gh = p[3]*(float)HH;
        key = gw*gh*(1.f/3.f);
        gb4 = make_float4(gx - 0.5f*gw, gy - 0.5f*gh, gx + 0.5f*gw, gy + 0.5f*gh);
        s_key[tidx] = key;
        s_tbox[tidx]  = make_float4(gx, gy, gw, gh);
        s_scale[tidx] = 2.f - p[2]*p[3];
        float best = -1.f; int bestn = 0;
        #pragma unroll
        for (int n = 0; n < 9; n++) {
            float ia = fminf(gw, c_aw[n]) * fminf(gh, c_ah[n]);
            float ua = gw*gh + c_aw[n]*c_ah[n] - ia;
            float r = ia / ua;
            if (r > best) { best = r; bestn = n; }
        }
        int gi = (int)floorf(gx), gj = (int)floorf(gy);
        if (bestn >= 6 && bestn <= 8 && gi < WW && gj < HH) {
            aprime = bestn - 6;
            cellt  = gj*WW + gi;
            cls    = tc[b*TT + tidx];
        }
    }
    __syncthreads();

    // ---- phase B: rank-sort + scatter ----
    if (tidx < TT) {
        int rank = 0;
        #pragma unroll 10
        for (int j = 0; j < TT; j++) {
            float kj = s_key[j];
            rank += (kj < key) || (kj == key && j < tidx);
        }
        s_gb[rank] = gb4;
        s_ag[rank] = key;
        if (aprime == a && cellt >= lo && cellt < lo + CPB) {
            atomicMax(&s_map[cellt - lo], tidx);
            atomicOr(&s_cb[cls>>5][cellt - lo], 1u << (cls & 31));
        }
    }
    __syncthreads();

    // ---- phase C: per-cell loss ----
    if (!live) { t0 = 0.f; t1 = 0.f; t2 = -40.f; t3 = -40.f; t4 = 0.f; }
    const int j = cell / WW, i = cell % WW;
    const float aw = (a==0) ? 1.5f : ((a==1) ? 2.375f : 5.f);
    const float ah = (a==0) ? 2.f  : ((a==1) ? 4.5f   : 3.5f);

    float px = sigmoidf_(t0) + (float)i;
    float py = sigmoidf_(t1) + (float)j;
    float pw = __expf(t2) * aw;
    float ph = __expf(t3) * ah;
    float p1x = px - 0.5f*pw, p2x = px + 0.5f*pw;
    float p1y = py - 0.5f*ph, p2y = py + 0.5f*ph;
    float ap3 = pw*ph*(1.f/3.f);

    float apm = ap3;
    #pragma unroll
    for (int o = 16; o; o >>= 1) apm = fmaxf(apm, __shfl_xor_sync(0xffffffffu, apm, o));
    const float cap = 2.f*apm;

    // ignore test: exists t with iou>0.5 <=> inter - ag/3 > ap/3
    float m = -3.0e38f;
    #pragma unroll 1
    for (int tt = 0; tt < TT; tt += 5) {
        if (s_ag[tt] >= cap) break;
        #pragma unroll
        for (int k = 0; k < 5; k++) {
            float4 g = s_gb[tt+k];
            float ix = fminf(g.z, p2x) - fmaxf(g.x, p1x);
            float iy = fminf(g.w, p2y) - fmaxf(g.y, p1y);
            float score = __fmaf_rn(fmaxf(ix, 0.f), fmaxf(iy, 0.f), -s_ag[tt+k]);
            m = fmaxf(m, score);
        }
    }
    const bool ignore = (m > ap3);

    float lc = 0.f, lcls = 0.f, lloc = 0.f;
    const int w = live ? s_map[tidx] : -1;

    if (w >= 0) {
        lc = softplusf_(-t4);
        float4 tbv = s_tbox[w];
        float  scl = s_scale[w];
        float b2w = tbv.z, b2h = tbv.w;
        float b2minx = tbv.x - 0.5f*b2w, b2maxx = tbv.x + 0.5f*b2w;
        float b2miny = tbv.y - 0.5f*b2h, b2maxy = tbv.y + 0.5f*b2h;
        float iwx = fmaxf(fminf(p2x, b2maxx) - fmaxf(p1x, b2minx), 0.f);
        float iwy = fmaxf(fminf(p2y, b2maxy) - fmaxf(p1y, b2miny), 0.f);
        float inter = iwx*iwy;
        float uni = pw*ph + b2w*b2h - inter;
        float iou = inter / fmaxf(uni, 1e-6f);
        float dx = px - tbv.x, dy = py - tbv.y;
        float cd = dx*dx + dy*dy;
        float ewx = fmaxf(fmaxf(p2x, b2maxx) - fminf(p1x, b2minx), 0.f);
        float ewy = fmaxf(fmaxf(p2y, b2maxy) - fminf(p1y, b2miny), 0.f);
        float ed = ewx*ewx + ewy*ewy;
        float ciou = iou - cd / fmaxf(ed, 1e-6f);
        float da = atanf(pw / fmaxf(ph, 1e-6f)) - atanf(b2w / fmaxf(b2h, 1e-6f));
        float v = 0.40528473456935108577f * da * da;  // 4/pi^2
        float alpha = v / fmaxf(1.f - iou + v, 1e-6f);
        lloc = (1.f - (ciou - alpha*v)) * scl;
    } else if (live && !ignore) {
        lc = softplusf_(t4);
    }

    // ---- phase D: cooperative class loss for this warp's positive lanes ----
    {
        const int lane = tidx & 31;
        const int wbase = tidx & ~31;
        unsigned posmask = __ballot_sync(0xffffffffu, w >= 0);
        while (posmask) {
            int p = __ffs(posmask) - 1;
            posmask &= posmask - 1;
            int ptid  = wbase + p;
            const float* pb = in + (size_t)ba*(5+NC)*WH + (lo + ptid);
            unsigned bb0 = s_cb[0][ptid];
            unsigned bb1 = s_cb[1][ptid];
            unsigned bb2 = s_cb[2][ptid];
            float x0 = __ldg(pb + (size_t)(5 + lane)*WH);
            float x1 = __ldg(pb + (size_t)(5 + lane + 32)*WH);
            float x2 = (lane < 16) ? __ldg(pb + (size_t)(5 + lane + 64)*WH) : 0.f;
            unsigned bit0 = (bb0 >> lane) & 1u;
            unsigned bit1 = (bb1 >> lane) & 1u;
            unsigned bit2 = (bb2 >> lane) & 1u;
            lcls += softplusf_(bit0 ? -x0 : x0);
            lcls += softplusf_(bit1 ? -x1 : x1);
            if (lane < 16) lcls += softplusf_(bit2 ? -x2 : x2);
        }
    }

    // ---- block reduce ----
    #pragma unroll
    for (int o = 16; o; o >>= 1) {
        lc   += __shfl_down_sync(0xffffffffu, lc,   o);
        lcls += __shfl_down_sync(0xffffffffu, lcls, o);
        lloc += __shfl_down_sync(0xffffffffu, lloc, o);
    }
    __shared__ float s_r[3][16];
    int wid = tidx >> 5, lane = tidx & 31;
    if (lane == 0) { s_r[0][wid] = lc; s_r[1][wid] = lcls; s_r[2][wid] = lloc; }
    __syncthreads();

    __shared__ bool s_last;
    const int bid = blockIdx.y*24 + blockIdx.x;
    if (tidx == 0) {
        float a0 = 0.f, a1 = 0.f, a2 = 0.f;
        #pragma unroll
        for (int k = 0; k < 16; k++) { a0 += s_r[0][k]; a1 += s_r[1][k]; a2 += s_r[2][k]; }
        g_part[bid]          = a0;
        g_part[bid +   NBLK] = a1;
        g_part[bid + 2*NBLK] = a2;
        __threadfence();
        s_last = (atomicAdd(&g_count, 1) == NBLK - 1);
    }
    __syncthreads();

    // ---- last block: final reduce + output ----
    if (s_last) {
        __threadfence();
        double a0 = 0.0, a1 = 0.0, a2 = 0.0;
        for (int k = tidx; k < NBLK; k += CPB) {
            a0 += (double)g_part[k];
            a1 += (double)g_part[k +   NBLK];
            a2 += (double)g_part[k + 2*NBLK];
        }
        #pragma unroll
        for (int o = 16; o; o >>= 1) {
            a0 += __shfl_down_sync(0xffffffffu, a0, o);
            a1 += __shfl_down_sync(0xffffffffu, a1, o);
            a2 += __shfl_down_sync(0xffffffffu, a2, o);
        }
        __shared__ double s_rd[3][16];
        if (lane == 0) { s_rd[0][wid] = a0; s_rd[1][wid] = a1; s_rd[2][wid] = a2; }
        __syncthreads();
        if (tidx == 0) {
            double c0 = 0.0, c1 = 0.0, c2 = 0.0;
            #pragma unroll
            for (int k = 0; k < 16; k++) { c0 += s_rd[0][k]; c1 += s_rd[1][k]; c2 += s_rd[2][k]; }
            float conf = (float)(c0 * (1.0/BSZ));
            float cls  = (float)(c1 * (1.0/BSZ));
            float loc  = (float)(c2 * (1.0/BSZ));
            out[0] = conf + cls + loc;
            out[1] = conf;
            out[2] = cls;
            out[3] = loc;
            g_count = 0;
        }
    }
}

extern "C" void kernel_launch(void* const* d_in, const int* in_sizes, int n_in,
                              void* d_out, int out_size)
{
    const float* in  = (const float*)d_in[0];
    const float* tbx = (const float*)d_in[1];
    const int*   tcl = (const int*)d_in[2];
    float* out = (float*)d_out;

    dim3 grid(BSZ*NA, NBY);
    yolo_fused<<<grid, CPB>>>(in, tbx, tcl, out);
}

// round 10
// speedup vs baseline: 1.0152x; 1.0152x over previous
#include <cuda_runtime.h>
#include <math.h>

#define BSZ 8
#define NA 3
#define HH 76
#define WW 76
#define WH (HH*WW)            // 5776
#define NC 80
#define TT 50
#define CPB 512               // cells per block
#define NBY ((WH + CPB - 1)/CPB)   // 12
#define NBLK (BSZ*NA*NBY)     // 288

// persistent device scratch (rewritten every run)
__device__ float g_part[3*NBLK];
__device__ int   g_count = 0;

// anchors / stride(=8)
__constant__ float c_aw[9] = {17.75f, 24.f, 57.375f, 4.5f, 9.5f, 9.f,   1.5f, 2.375f, 5.f};
__constant__ float c_ah[9] = {13.75f, 30.375f, 50.125f, 9.375f, 6.875f, 18.25f, 2.f, 4.5f, 3.5f};

__device__ __forceinline__ float sigmoidf_(float x) { return 1.f/(1.f+__expf(-x)); }
// bce(sigmoid(x),1)=softplus(-x), bce(sigmoid(x),0)=softplus(x); fast MUFU version
__device__ __forceinline__ float softplusf_(float x) {
    return fmaxf(x, 0.f) + __logf(1.f + __expf(-fabsf(x)));
}

__global__ __launch_bounds__(CPB) void yolo_fused(const float* __restrict__ in,
                                                  const float* __restrict__ tb,
                                                  const int*   __restrict__ tc,
                                                  float* __restrict__ out)
{
    const int ba = blockIdx.x;                 // 0..23
    const int b  = ba / NA, a = ba % NA;
    const int lo = blockIdx.y * CPB;
    const int tidx = threadIdx.x;
    const int cell0 = lo + tidx;
    const bool live = cell0 < WH;
    const int cell = live ? cell0 : 0;

    __shared__ float4   s_gb[TT];      // sorted corner boxes
    __shared__ float    s_ag[TT];      // sorted gt area/3 (ascending)
    __shared__ float    s_key[TT];
    __shared__ float4   s_tbox[TT];    // unsorted (gx,gy,gw,gh)
    __shared__ float    s_scale[TT];   // unsorted 2 - sx*sy
    __shared__ int      s_map[CPB];
    __shared__ unsigned s_cb[3][CPB];

    // ---- hoisted input loads (latency overlaps target prep + barriers) ----
    const float* base = in + (size_t)ba*(5+NC)*WH + cell;
    float t0 = __ldg(base);
    float t1 = __ldg(base + WH);
    float t2 = __ldg(base + 2*WH);
    float t3 = __ldg(base + 3*WH);
    float t4 = __ldg(base + 4*WH);

    // ---- phase A: init + per-target prep ----
    s_map[tidx] = -1;
    s_cb[0][tidx] = 0u; s_cb[1][tidx] = 0u; s_cb[2][tidx] = 0u;

    float key = 0.f; float4 gb4; int cellt = -1, aprime = -1, cls = 0;
    if (tidx < TT) {
        const float* p = tb + (size_t)(b*TT + tidx)*4;
        float gx = p[0]*(float)WW, gy = p[1]*(float)HH;
        float gw = p[2]*(float)WW, gh = p[3]*(float)HH;
        key = gw*gh*(1.f/3.f);
        gb4 = make_float4(gx - 0.5f*gw, gy - 0.5f*gh, gx + 0.5f*gw, gy + 0.5f*gh);
        s_key[tidx] = key;
        s_tbox[tidx]  = make_float4(gx, gy, gw, gh);
        s_scale[tidx] = 2.f - p[2]*p[3];
        float best = -1.f; int bestn = 0;
        #pragma unroll
        for (int n = 0; n < 9; n++) {
            float ia = fminf(gw, c_aw[n]) * fminf(gh, c_ah[n]);
            float ua = gw*gh + c_aw[n]*c_ah[n] - ia;
            float r = ia / ua;
            if (r > best) { best = r; bestn = n; }
        }
        int gi = (int)floorf(gx), gj = (int)floorf(gy);
        if (bestn >= 6 && bestn <= 8 && gi < WW && gj < HH) {
            aprime = bestn - 6;
            cellt  = gj*WW + gi;
            cls    = tc[b*TT + tidx];
        }
    }
    __syncthreads();

    // ---- phase B: rank-sort + scatter ----
    if (tidx < TT) {
        int rank = 0;
        #pragma unroll 10
        for (int j = 0; j < TT; j++) {
            float kj = s_key[j];
            rank += (kj < key) || (kj == key && j < tidx);
        }
        s_gb[rank] = gb4;
        s_ag[rank] = key;
        if (aprime == a && cellt >= lo && cellt < lo + CPB) {
            atomicMax(&s_map[cellt - lo], tidx);
            atomicOr(&s_cb[cls>>5][cellt - lo], 1u << (cls & 31));
        }
    }
    __syncthreads();

    // ---- phase C: per-cell loss ----
    if (!live) { t0 = 0.f; t1 = 0.f; t2 = -40.f; t3 = -40.f; t4 = 0.f; }
    const int j = cell / WW, i = cell % WW;
    const float aw = (a==0) ? 1.5f : ((a==1) ? 2.375f : 5.f);
    const float ah = (a==0) ? 2.f  : ((a==1) ? 4.5f   : 3.5f);

    float px = sigmoidf_(t0) + (float)i;
    float py = sigmoidf_(t1) + (float)j;
    float pw = __expf(t2) * aw;
    float ph = __expf(t3) * ah;
    float p1x = px - 0.5f*pw, p2x = px + 0.5f*pw;
    float p1y = py - 0.5f*ph, p2y = py + 0.5f*ph;
    float ap3 = pw*ph*(1.f/3.f);

    float apm = ap3;
    #pragma unroll
    for (int o = 16; o; o >>= 1) apm = fmaxf(apm, __shfl_xor_sync(0xffffffffu, apm, o));
    const float cap = 2.f*apm;

    // ignore test: exists t with iou>0.5 <=> inter - ag/3 > ap/3
    float m = -3.0e38f;
    #pragma unroll 1
    for (int tt = 0; tt < TT; tt += 5) {
        if (s_ag[tt] >= cap) break;
        #pragma unroll
        for (int k = 0; k < 5; k++) {
            float4 g = s_gb[tt+k];
            float ix = fminf(g.z, p2x) - fmaxf(g.x, p1x);
            float iy = fminf(g.w, p2y) - fmaxf(g.y, p1y);
            float score = __fmaf_rn(fmaxf(ix, 0.f), fmaxf(iy, 0.f), -s_ag[tt+k]);
            m = fmaxf(m, score);
        }
    }
    const bool ignore = (m > ap3);

    float lc = 0.f, lcls = 0.f, lloc = 0.f;
    const int w = live ? s_map[tidx] : -1;

    if (w >= 0) {
        lc = softplusf_(-t4);
        float4 tbv = s_tbox[w];
        float  scl = s_scale[w];
        float b2w = tbv.z, b2h = tbv.w;
        float b2minx = tbv.x - 0.5f*b2w, b2maxx = tbv.x + 0.5f*b2w;
        float b2miny = tbv.y - 0.5f*b2h, b2maxy = tbv.y + 0.5f*b2h;
        float iwx = fmaxf(fminf(p2x, b2maxx) - fmaxf(p1x, b2minx), 0.f);
        float iwy = fmaxf(fminf(p2y, b2maxy) - fmaxf(p1y, b2miny), 0.f);
        float inter = iwx*iwy;
        float uni = pw*ph + b2w*b2h - inter;
        float iou = inter / fmaxf(uni, 1e-6f);
        float dx = px - tbv.x, dy = py - tbv.y;
        float cd = dx*dx + dy*dy;
        float ewx = fmaxf(fmaxf(p2x, b2maxx) - fminf(p1x, b2minx), 0.f);
        float ewy = fmaxf(fmaxf(p2y, b2maxy) - fminf(p1y, b2miny), 0.f);
        float ed = ewx*ewx + ewy*ewy;
        float ciou = iou - cd / fmaxf(ed, 1e-6f);
        float da = atanf(pw / fmaxf(ph, 1e-6f)) - atanf(b2w / fmaxf(b2h, 1e-6f));
        float v = 0.40528473456935108577f * da * da;  // 4/pi^2
        float alpha = v / fmaxf(1.f - iou + v, 1e-6f);
        lloc = (1.f - (ciou - alpha*v)) * scl;
    } else if (live && !ignore) {
        lc = softplusf_(t4);
    }

    // ---- phase D: cooperative class loss for this warp's positive lanes ----
    {
        const int lane = tidx & 31;
        const int wbase = tidx & ~31;
        unsigned posmask = __ballot_sync(0xffffffffu, w >= 0);
        while (posmask) {
            int p = __ffs(posmask) - 1;
            posmask &= posmask - 1;
            int ptid  = wbase + p;
            const float* pb = in + (size_t)ba*(5+NC)*WH + (lo + ptid);
            unsigned bb0 = s_cb[0][ptid];
            unsigned bb1 = s_cb[1][ptid];
            unsigned bb2 = s_cb[2][ptid];
            float x0 = __ldg(pb + (size_t)(5 + lane)*WH);
            float x1 = __ldg(pb + (size_t)(5 + lane + 32)*WH);
            float x2 = (lane < 16) ? __ldg(pb + (size_t)(5 + lane + 64)*WH) : 0.f;
            unsigned bit0 = (bb0 >> lane) & 1u;
            unsigned bit1 = (bb1 >> lane) & 1u;
            unsigned bit2 = (bb2 >> lane) & 1u;
            lcls += softplusf_(bit0 ? -x0 : x0);
            lcls += softplusf_(bit1 ? -x1 : x1);
            if (lane < 16) lcls += softplusf_(bit2 ? -x2 : x2);
        }
    }

    // ---- block reduce ----
    #pragma unroll
    for (int o = 16; o; o >>= 1) {
        lc   += __shfl_down_sync(0xffffffffu, lc,   o);
        lcls += __shfl_down_sync(0xffffffffu, lcls, o);
        lloc += __shfl_down_sync(0xffffffffu, lloc, o);
    }
    __shared__ float s_r[3][16];
    int wid = tidx >> 5, lane = tidx & 31;
    if (lane == 0) { s_r[0][wid] = lc; s_r[1][wid] = lcls; s_r[2][wid] = lloc; }
    __syncthreads();

    __shared__ bool s_last;
    const int bid = blockIdx.y*24 + blockIdx.x;
    if (tidx == 0) {
        float a0 = 0.f, a1 = 0.f, a2 = 0.f;
        #pragma unroll
        for (int k = 0; k < 16; k++) { a0 += s_r[0][k]; a1 += s_r[1][k]; a2 += s_r[2][k]; }
        g_part[bid]          = a0;
        g_part[bid +   NBLK] = a1;
        g_part[bid + 2*NBLK] = a2;
        __threadfence();
        s_last = (atomicAdd(&g_count, 1) == NBLK - 1);
    }
    __syncthreads();

    // ---- last block: final reduce + output ----
    if (s_last) {
        __threadfence();
        double a0 = 0.0, a1 = 0.0, a2 = 0.0;
        for (int k = tidx; k < NBLK; k += CPB) {
            a0 += (double)g_part[k];
            a1 += (double)g_part[k +   NBLK];
            a2 += (double)g_part[k + 2*NBLK];
        }
        #pragma unroll
        for (int o = 16; o; o >>= 1) {
            a0 += __shfl_down_sync(0xffffffffu, a0, o);
            a1 += __shfl_down_sync(0xffffffffu, a1, o);
            a2 += __shfl_down_sync(0xffffffffu, a2, o);
        }
        __shared__ double s_rd[3][16];
        if (lane == 0) { s_rd[0][wid] = a0; s_rd[1][wid] = a1; s_rd[2][wid] = a2; }
        __syncthreads();
        if (tidx == 0) {
            double c0 = 0.0, c1 = 0.0, c2 = 0.0;
            #pragma unroll
            for (int k = 0; k < 16; k++) { c0 += s_rd[0][k]; c1 += s_rd[1][k]; c2 += s_rd[2][k]; }
            float conf = (float)(c0 * (1.0/BSZ));
            float cls  = (float)(c1 * (1.0/BSZ));
            float loc  = (float)(c2 * (1.0/BSZ));
            out[0] = conf + cls + loc;
            out[1] = conf;
            out[2] = cls;
            out[3] = loc;
            g_count = 0;
        }
    }
}

extern "C" void kernel_launch(void* const* d_in, const int* in_sizes, int n_in,
                              void* d_out, int out_size)
{
    const float* in  = (const float*)d_in[0];
    const float* tbx = (const float*)d_in[1];
    const int*   tcl = (const int*)d_in[2];
    float* out = (float*)d_out;

    dim3 grid(BSZ*NA, NBY);
    yolo_fused<<<grid, CPB>>>(in, tbx, tcl, out);
}

// round 11
// speedup vs baseline: 1.0171x; 1.0019x over previous
#include <cuda_runtime.h>
#include <math.h>

#define BSZ 8
#define NA 3
#define HH 76
#define WW 76
#define WH (HH*WW)            // 5776
#define NC 80
#define TT 50
#define CPB 512               // cells per block
#define NBY ((WH + CPB - 1)/CPB)   // 12
#define NBLK (BSZ*NA*NBY)     // 288

// persistent device scratch (rewritten every run)
__device__ float g_part[3*NBLK];
__device__ int   g_count = 0;

// anchors / stride(=8)
__constant__ float c_aw[9] = {17.75f, 24.f, 57.375f, 4.5f, 9.5f, 9.f,   1.5f, 2.375f, 5.f};
__constant__ float c_ah[9] = {13.75f, 30.375f, 50.125f, 9.375f, 6.875f, 18.25f, 2.f, 4.5f, 3.5f};

__device__ __forceinline__ float sigmoidf_(float x) { return 1.f/(1.f+__expf(-x)); }
// bce(sigmoid(x),1)=softplus(-x), bce(sigmoid(x),0)=softplus(x); fast MUFU version
__device__ __forceinline__ float softplusf_(float x) {
    return fmaxf(x, 0.f) + __logf(1.f + __expf(-fabsf(x)));
}

__global__ __launch_bounds__(CPB) void yolo_fused(const float* __restrict__ in,
                                                  const float* __restrict__ tb,
                                                  const int*   __restrict__ tc,
                                                  float* __restrict__ out)
{
    const int ba = blockIdx.x;                 // 0..23
    const int b  = ba / NA, a = ba % NA;
    const int lo = blockIdx.y * CPB;
    const int tidx = threadIdx.x;
    const int cell0 = lo + tidx;
    const bool live = cell0 < WH;
    const int cell = live ? cell0 : 0;

    __shared__ float4   s_gb[TT];      // sorted corner boxes
    __shared__ float    s_ag[TT];      // sorted gt area/3 (ascending)
    __shared__ float    s_key[TT];
    __shared__ float4   s_tbox[TT];    // unsorted (gx,gy,gw,gh)
    __shared__ float    s_scale[TT];   // unsorted 2 - sx*sy
    __shared__ int      s_map[CPB];
    __shared__ unsigned s_cb[3][CPB];

    // ---- hoisted input loads (latency overlaps target prep + barriers) ----
    const float* base = in + (size_t)ba*(5+NC)*WH + cell;
    float t0 = __ldg(base);
    float t1 = __ldg(base + WH);
    float t2 = __ldg(base + 2*WH);
    float t3 = __ldg(base + 3*WH);
    float t4 = __ldg(base + 4*WH);

    // ---- phase A: init + per-target prep ----
    s_map[tidx] = -1;
    s_cb[0][tidx] = 0u; s_cb[1][tidx] = 0u; s_cb[2][tidx] = 0u;

    float key = 0.f; float4 gb4; int cellt = -1, aprime = -1, cls = 0;
    if (tidx < TT) {
        const float* p = tb + (size_t)(b*TT + tidx)*4;
        float gx = p[0]*(float)WW, gy = p[1]*(float)HH;
        float gw = p[2]*(float)WW, gh = p[3]*(float)HH;
        key = gw*gh*(1.f/3.f);
        gb4 = make_float4(gx - 0.5f*gw, gy - 0.5f*gh, gx + 0.5f*gw, gy + 0.5f*gh);
        s_key[tidx] = key;
        s_tbox[tidx]  = make_float4(gx, gy, gw, gh);
        s_scale[tidx] = 2.f - p[2]*p[3];
        float best = -1.f; int bestn = 0;
        #pragma unroll
        for (int n = 0; n < 9; n++) {
            float ia = fminf(gw, c_aw[n]) * fminf(gh, c_ah[n]);
            float ua = gw*gh + c_aw[n]*c_ah[n] - ia;
            float r = ia / ua;
            if (r > best) { best = r; bestn = n; }
        }
        int gi = (int)floorf(gx), gj = (int)floorf(gy);
        if (bestn >= 6 && bestn <= 8 && gi < WW && gj < HH) {
            aprime = bestn - 6;
            cellt  = gj*WW + gi;
            cls    = tc[b*TT + tidx];
        }
    }
    __syncthreads();

    // ---- phase B: rank-sort + scatter ----
    if (tidx < TT) {
        int rank = 0;
        #pragma unroll 10
        for (int j = 0; j < TT; j++) {
            float kj = s_key[j];
            rank += (kj < key) || (kj == key && j < tidx);
        }
        s_gb[rank] = gb4;
        s_ag[rank] = key;
        if (aprime == a && cellt >= lo && cellt < lo + CPB) {
            atomicMax(&s_map[cellt - lo], tidx);
            atomicOr(&s_cb[cls>>5][cellt - lo], 1u << (cls & 31));
        }
    }
    __syncthreads();

    // ---- phase C: per-cell loss ----
    if (!live) { t0 = 0.f; t1 = 0.f; t2 = -40.f; t3 = -40.f; t4 = 0.f; }
    const int j = cell / WW, i = cell % WW;
    const float aw = (a==0) ? 1.5f : ((a==1) ? 2.375f : 5.f);
    const float ah = (a==0) ? 2.f  : ((a==1) ? 4.5f   : 3.5f);

    float px = sigmoidf_(t0) + (float)i;
    float py = sigmoidf_(t1) + (float)j;
    float pw = __expf(t2) * aw;
    float ph = __expf(t3) * ah;
    float p1x = px - 0.5f*pw, p2x = px + 0.5f*pw;
    float p1y = py - 0.5f*ph, p2y = py + 0.5f*ph;
    float ap3 = pw*ph*(1.f/3.f);

    float apm = ap3;
    #pragma unroll
    for (int o = 16; o; o >>= 1) apm = fmaxf(apm, __shfl_xor_sync(0xffffffffu, apm, o));
    const float cap = 2.f*apm;

    // ignore test: exists t with iou>0.5 <=> inter - ag/3 > ap/3
    float m = -3.0e38f;
    #pragma unroll 1
    for (int tt = 0; tt < TT; tt += 5) {
        if (s_ag[tt] >= cap) break;
        #pragma unroll
        for (int k = 0; k < 5; k++) {
            float4 g = s_gb[tt+k];
            float ix = fminf(g.z, p2x) - fmaxf(g.x, p1x);
            float iy = fminf(g.w, p2y) - fmaxf(g.y, p1y);
            float score = __fmaf_rn(fmaxf(ix, 0.f), fmaxf(iy, 0.f), -s_ag[tt+k]);
            m = fmaxf(m, score);
        }
    }
    const bool ignore = (m > ap3);

    float lc = 0.f, lcls = 0.f, lloc = 0.f;
    const int w = live ? s_map[tidx] : -1;

    if (w >= 0) {
        lc = softplusf_(-t4);
        float4 tbv = s_tbox[w];
        float  scl = s_scale[w];
        float b2w = tbv.z, b2h = tbv.w;
        float b2minx = tbv.x - 0.5f*b2w, b2maxx = tbv.x + 0.5f*b2w;
        float b2miny = tbv.y - 0.5f*b2h, b2maxy = tbv.y + 0.5f*b2h;
        float iwx = fmaxf(fminf(p2x, b2maxx) - fmaxf(p1x, b2minx), 0.f);
        float iwy = fmaxf(fminf(p2y, b2maxy) - fmaxf(p1y, b2miny), 0.f);
        float inter = iwx*iwy;
        float uni = pw*ph + b2w*b2h - inter;
        float iou = inter / fmaxf(uni, 1e-6f);
        float dx = px - tbv.x, dy = py - tbv.y;
        float cd = dx*dx + dy*dy;
        float ewx = fmaxf(fmaxf(p2x, b2maxx) - fminf(p1x, b2minx), 0.f);
        float ewy = fmaxf(fmaxf(p2y, b2maxy) - fminf(p1y, b2miny), 0.f);
        float ed = ewx*ewx + ewy*ewy;
        float ciou = iou - cd / fmaxf(ed, 1e-6f);
        float da = atanf(pw / fmaxf(ph, 1e-6f)) - atanf(b2w / fmaxf(b2h, 1e-6f));
        float v = 0.40528473456935108577f * da * da;  // 4/pi^2
        float alpha = v / fmaxf(1.f - iou + v, 1e-6f);
        lloc = (1.f - (ciou - alpha*v)) * scl;
    } else if (live && !ignore) {
        lc = softplusf_(t4);
    }

    // ---- phase D: cooperative class loss for this warp's positive lanes ----
    {
        const int lane = tidx & 31;
        const int wbase = tidx & ~31;
        unsigned posmask = __ballot_sync(0xffffffffu, w >= 0);
        while (posmask) {
            int p = __ffs(posmask) - 1;
            posmask &= posmask - 1;
            int ptid  = wbase + p;
            const float* pb = in + (size_t)ba*(5+NC)*WH + (lo + ptid);
            unsigned bb0 = s_cb[0][ptid];
            unsigned bb1 = s_cb[1][ptid];
            unsigned bb2 = s_cb[2][ptid];
            float x0 = __ldg(pb + (size_t)(5 + lane)*WH);
            float x1 = __ldg(pb + (size_t)(5 + lane + 32)*WH);
            float x2 = (lane < 16) ? __ldg(pb + (size_t)(5 + lane + 64)*WH) : 0.f;
            unsigned bit0 = (bb0 >> lane) & 1u;
            unsigned bit1 = (bb1 >> lane) & 1u;
            unsigned bit2 = (bb2 >> lane) & 1u;
            lcls += softplusf_(bit0 ? -x0 : x0);
            lcls += softplusf_(bit1 ? -x1 : x1);
            if (lane < 16) lcls += softplusf_(bit2 ? -x2 : x2);
        }
    }

    // ---- block reduce ----
    #pragma unroll
    for (int o = 16; o; o >>= 1) {
        lc   += __shfl_down_sync(0xffffffffu, lc,   o);
        lcls += __shfl_down_sync(0xffffffffu, lcls, o);
        lloc += __shfl_down_sync(0xffffffffu, lloc, o);
    }
    __shared__ float s_r[3][16];
    int wid = tidx >> 5, lane = tidx & 31;
    if (lane == 0) { s_r[0][wid] = lc; s_r[1][wid] = lcls; s_r[2][wid] = lloc; }
    __syncthreads();

    __shared__ bool s_last;
    const int bid = blockIdx.y*24 + blockIdx.x;
    if (tidx == 0) {
        float a0 = 0.f, a1 = 0.f, a2 = 0.f;
        #pragma unroll
        for (int k = 0; k < 16; k++) { a0 += s_r[0][k]; a1 += s_r[1][k]; a2 += s_r[2][k]; }
        g_part[bid]          = a0;
        g_part[bid +   NBLK] = a1;
        g_part[bid + 2*NBLK] = a2;
        __threadfence();
        s_last = (atomicAdd(&g_count, 1) == NBLK - 1);
    }
    __syncthreads();

    // ---- last block: final reduce + output ----
    if (s_last) {
        __threadfence();
        double a0 = 0.0, a1 = 0.0, a2 = 0.0;
        for (int k = tidx; k < NBLK; k += CPB) {
            a0 += (double)g_part[k];
            a1 += (double)g_part[k +   NBLK];
            a2 += (double)g_part[k + 2*NBLK];
        }
        #pragma unroll
        for (int o = 16; o; o >>= 1) {
            a0 += __shfl_down_sync(0xffffffffu, a0, o);
            a1 += __shfl_down_sync(0xffffffffu, a1, o);
            a2 += __shfl_down_sync(0xffffffffu, a2, o);
        }
        __shared__ double s_rd[3][16];
        if (lane == 0) { s_rd[0][wid] = a0; s_rd[1][wid] = a1; s_rd[2][wid] = a2; }
        __syncthreads();
        if (tidx == 0) {
            double c0 = 0.0, c1 = 0.0, c2 = 0.0;
            #pragma unroll
            for (int k = 0; k < 16; k++) { c0 += s_rd[0][k]; c1 += s_rd[1][k]; c2 += s_rd[2][k]; }
            float conf = (float)(c0 * (1.0/BSZ));
            float cls  = (float)(c1 * (1.0/BSZ));
            float loc  = (float)(c2 * (1.0/BSZ));
            out[0] = conf + cls + loc;
            out[1] = conf;
            out[2] = cls;
            out[3] = loc;
            g_count = 0;
        }
    }
}

extern "C" void kernel_launch(void* const* d_in, const int* in_sizes, int n_in,
                              void* d_out, int out_size)
{
    const float* in  = (const float*)d_in[0];
    const float* tbx = (const float*)d_in[1];
    const int*   tcl = (const int*)d_in[2];
    float* out = (float*)d_out;

    dim3 grid(BSZ*NA, NBY);
    yolo_fused<<<grid, CPB>>>(in, tbx, tcl, out);
}

// round 12
// speedup vs baseline: 1.0190x; 1.0019x over previous
#include <cuda_runtime.h>
#include <math.h>

#define BSZ 8
#define NA 3
#define HH 76
#define WW 76
#define WH (HH*WW)            // 5776
#define NC 80
#define TT 50
#define CPB 512               // cells per block
#define NBY ((WH + CPB - 1)/CPB)   // 12
#define NBLK (BSZ*NA*NBY)     // 288

// persistent device scratch (rewritten every run)
__device__ float g_part[3*NBLK];
__device__ int   g_count = 0;

// anchors / stride(=8)
__constant__ float c_aw[9] = {17.75f, 24.f, 57.375f, 4.5f, 9.5f, 9.f,   1.5f, 2.375f, 5.f};
__constant__ float c_ah[9] = {13.75f, 30.375f, 50.125f, 9.375f, 6.875f, 18.25f, 2.f, 4.5f, 3.5f};

__device__ __forceinline__ float sigmoidf_(float x) { return 1.f/(1.f+__expf(-x)); }
// bce(sigmoid(x),1)=softplus(-x), bce(sigmoid(x),0)=softplus(x); fast MUFU version
__device__ __forceinline__ float softplusf_(float x) {
    return fmaxf(x, 0.f) + __logf(1.f + __expf(-fabsf(x)));
}

__global__ __launch_bounds__(CPB) void yolo_fused(const float* __restrict__ in,
                                                  const float* __restrict__ tb,
                                                  const int*   __restrict__ tc,
                                                  float* __restrict__ out)
{
    const int ba = blockIdx.x;                 // 0..23
    const int b  = ba / NA, a = ba % NA;
    const int lo = blockIdx.y * CPB;
    const int tidx = threadIdx.x;
    const int cell0 = lo + tidx;
    const bool live = cell0 < WH;
    const int cell = live ? cell0 : 0;

    __shared__ float4   s_gb[TT];      // sorted corner boxes
    __shared__ float    s_ag[TT];      // sorted gt area/3 (ascending)
    __shared__ float    s_key[TT];
    __shared__ float4   s_tbox[TT];    // unsorted (gx,gy,gw,gh)
    __shared__ float    s_scale[TT];   // unsorted 2 - sx*sy
    __shared__ int      s_map[CPB];
    __shared__ unsigned s_cb[3][CPB];

    // ---- hoisted input loads (latency overlaps target prep + barriers) ----
    const float* base = in + (size_t)ba*(5+NC)*WH + cell;
    float t0 = __ldg(base);
    float t1 = __ldg(base + WH);
    float t2 = __ldg(base + 2*WH);
    float t3 = __ldg(base + 3*WH);
    float t4 = __ldg(base + 4*WH);

    // ---- phase A: init + per-target prep ----
    s_map[tidx] = -1;
    s_cb[0][tidx] = 0u; s_cb[1][tidx] = 0u; s_cb[2][tidx] = 0u;

    float key = 0.f; float4 gb4; int cellt = -1, aprime = -1, cls = 0;
    if (tidx < TT) {
        const float* p = tb + (size_t)(b*TT + tidx)*4;
        float gx = p[0]*(float)WW, gy = p[1]*(float)HH;
        float gw = p[2]*(float)WW, gh = p[3]*(float)HH;
        key = gw*gh*(1.f/3.f);
        gb4 = make_float4(gx - 0.5f*gw, gy - 0.5f*gh, gx + 0.5f*gw, gy + 0.5f*gh);
        s_key[tidx] = key;
        s_tbox[tidx]  = make_float4(gx, gy, gw, gh);
        s_scale[tidx] = 2.f - p[2]*p[3];
        float best = -1.f; int bestn = 0;
        #pragma unroll
        for (int n = 0; n < 9; n++) {
            float ia = fminf(gw, c_aw[n]) * fminf(gh, c_ah[n]);
            float ua = gw*gh + c_aw[n]*c_ah[n] - ia;
            float r = ia / ua;
            if (r > best) { best = r; bestn = n; }
        }
        int gi = (int)floorf(gx), gj = (int)floorf(gy);
        if (bestn >= 6 && bestn <= 8 && gi < WW && gj < HH) {
            aprime = bestn - 6;
            cellt  = gj*WW + gi;
            cls    = tc[b*TT + tidx];
        }
    }
    __syncthreads();

    // ---- phase B: rank-sort + scatter ----
    if (tidx < TT) {
        int rank = 0;
        #pragma unroll 10
        for (int j = 0; j < TT; j++) {
            float kj = s_key[j];
            rank += (kj < key) || (kj == key && j < tidx);
        }
        s_gb[rank] = gb4;
        s_ag[rank] = key;
        if (aprime == a && cellt >= lo && cellt < lo + CPB) {
            atomicMax(&s_map[cellt - lo], tidx);
            atomicOr(&s_cb[cls>>5][cellt - lo], 1u << (cls & 31));
        }
    }
    __syncthreads();

    // ---- phase C: per-cell loss ----
    if (!live) { t0 = 0.f; t1 = 0.f; t2 = -40.f; t3 = -40.f; t4 = 0.f; }
    const int j = cell / WW, i = cell % WW;
    const float aw = (a==0) ? 1.5f : ((a==1) ? 2.375f : 5.f);
    const float ah = (a==0) ? 2.f  : ((a==1) ? 4.5f   : 3.5f);

    float px = sigmoidf_(t0) + (float)i;
    float py = sigmoidf_(t1) + (float)j;
    float pw = __expf(t2) * aw;
    float ph = __expf(t3) * ah;
    float p1x = px - 0.5f*pw, p2x = px + 0.5f*pw;
    float p1y = py - 0.5f*ph, p2y = py + 0.5f*ph;
    float ap3 = pw*ph*(1.f/3.f);

    float apm = ap3;
    #pragma unroll
    for (int o = 16; o; o >>= 1) apm = fmaxf(apm, __shfl_xor_sync(0xffffffffu, apm, o));
    const float cap = 2.f*apm;

    // ignore test: exists t with iou>0.5 <=> inter - ag/3 > ap/3
    float m = -3.0e38f;
    #pragma unroll 1
    for (int tt = 0; tt < TT; tt += 5) {
        if (s_ag[tt] >= cap) break;
        #pragma unroll
        for (int k = 0; k < 5; k++) {
            float4 g = s_gb[tt+k];
            float ix = fminf(g.z, p2x) - fmaxf(g.x, p1x);
            float iy = fminf(g.w, p2y) - fmaxf(g.y, p1y);
            float score = __fmaf_rn(fmaxf(ix, 0.f), fmaxf(iy, 0.f), -s_ag[tt+k]);
            m = fmaxf(m, score);
        }
    }
    const bool ignore = (m > ap3);

    float lc = 0.f, lcls = 0.f, lloc = 0.f;
    const int w = live ? s_map[tidx] : -1;

    if (w >= 0) {
        lc = softplusf_(-t4);
        float4 tbv = s_tbox[w];
        float  scl = s_scale[w];
        float b2w = tbv.z, b2h = tbv.w;
        float b2minx = tbv.x - 0.5f*b2w, b2maxx = tbv.x + 0.5f*b2w;
        float b2miny = tbv.y - 0.5f*b2h, b2maxy = tbv.y + 0.5f*b2h;
        float iwx = fmaxf(fminf(p2x, b2maxx) - fmaxf(p1x, b2minx), 0.f);
        float iwy = fmaxf(fminf(p2y, b2maxy) - fmaxf(p1y, b2miny), 0.f);
        float inter = iwx*iwy;
        float uni = pw*ph + b2w*b2h - inter;
        float iou = inter / fmaxf(uni, 1e-6f);
        float dx = px - tbv.x, dy = py - tbv.y;
        float cd = dx*dx + dy*dy;
        float ewx = fmaxf(fmaxf(p2x, b2maxx) - fminf(p1x, b2minx), 0.f);
        float ewy = fmaxf(fmaxf(p2y, b2maxy) - fminf(p1y, b2miny), 0.f);
        float ed = ewx*ewx + ewy*ewy;
        float ciou = iou - cd / fmaxf(ed, 1e-6f);
        float da = atanf(pw / fmaxf(ph, 1e-6f)) - atanf(b2w / fmaxf(b2h, 1e-6f));
        float v = 0.40528473456935108577f * da * da;  // 4/pi^2
        float alpha = v / fmaxf(1.f - iou + v, 1e-6f);
        lloc = (1.f - (ciou - alpha*v)) * scl;
    } else if (live && !ignore) {
        lc = softplusf_(t4);
    }

    // ---- phase D: cooperative class loss for this warp's positive lanes ----
    {
        const int lane = tidx & 31;
        const int wbase = tidx & ~31;
        unsigned posmask = __ballot_sync(0xffffffffu, w >= 0);
        while (posmask) {
            int p = __ffs(posmask) - 1;
            posmask &= posmask - 1;
            int ptid  = wbase + p;
            const float* pb = in + (size_t)ba*(5+NC)*WH + (lo + ptid);
            unsigned bb0 = s_cb[0][ptid];
            unsigned bb1 = s_cb[1][ptid];
            unsigned bb2 = s_cb[2][ptid];
            float x0 = __ldg(pb + (size_t)(5 + lane)*WH);
            float x1 = __ldg(pb + (size_t)(5 + lane + 32)*WH);
            float x2 = (lane < 16) ? __ldg(pb + (size_t)(5 + lane + 64)*WH) : 0.f;
            unsigned bit0 = (bb0 >> lane) & 1u;
            unsigned bit1 = (bb1 >> lane) & 1u;
            unsigned bit2 = (bb2 >> lane) & 1u;
            lcls += softplusf_(bit0 ? -x0 : x0);
            lcls += softplusf_(bit1 ? -x1 : x1);
            if (lane < 16) lcls += softplusf_(bit2 ? -x2 : x2);
        }
    }

    // ---- block reduce ----
    #pragma unroll
    for (int o = 16; o; o >>= 1) {
        lc   += __shfl_down_sync(0xffffffffu, lc,   o);
        lcls += __shfl_down_sync(0xffffffffu, lcls, o);
        lloc += __shfl_down_sync(0xffffffffu, lloc, o);
    }
    __shared__ float s_r[3][16];
    int wid = tidx >> 5, lane = tidx & 31;
    if (lane == 0) { s_r[0][wid] = lc; s_r[1][wid] = lcls; s_r[2][wid] = lloc; }
    __syncthreads();

    __shared__ bool s_last;
    const int bid = blockIdx.y*24 + blockIdx.x;
    if (tidx == 0) {
        float a0 = 0.f, a1 = 0.f, a2 = 0.f;
        #pragma unroll
        for (int k = 0; k < 16; k++) { a0 += s_r[0][k]; a1 += s_r[1][k]; a2 += s_r[2][k]; }
        g_part[bid]          = a0;
        g_part[bid +   NBLK] = a1;
        g_part[bid + 2*NBLK] = a2;
        __threadfence();
        s_last = (atomicAdd(&g_count, 1) == NBLK - 1);
    }
    __syncthreads();

    // ---- last block: final reduce + output ----
    if (s_last) {
        __threadfence();
        double a0 = 0.0, a1 = 0.0, a2 = 0.0;
        for (int k = tidx; k < NBLK; k += CPB) {
            a0 += (double)g_part[k];
            a1 += (double)g_part[k +   NBLK];
            a2 += (double)g_part[k + 2*NBLK];
        }
        #pragma unroll
        for (int o = 16; o; o >>= 1) {
            a0 += __shfl_down_sync(0xffffffffu, a0, o);
            a1 += __shfl_down_sync(0xffffffffu, a1, o);
            a2 += __shfl_down_sync(0xffffffffu, a2, o);
        }
        __shared__ double s_rd[3][16];
        if (lane == 0) { s_rd[0][wid] = a0; s_rd[1][wid] = a1; s_rd[2][wid] = a2; }
        __syncthreads();
        if (tidx == 0) {
            double c0 = 0.0, c1 = 0.0, c2 = 0.0;
            #pragma unroll
            for (int k = 0; k < 16; k++) { c0 += s_rd[0][k]; c1 += s_rd[1][k]; c2 += s_rd[2][k]; }
            float conf = (float)(c0 * (1.0/BSZ));
            float cls  = (float)(c1 * (1.0/BSZ));
            float loc  = (float)(c2 * (1.0/BSZ));
            out[0] = conf + cls + loc;
            out[1] = conf;
            out[2] = cls;
            out[3] = loc;
            g_count = 0;
        }
    }
}

extern "C" void kernel_launch(void* const* d_in, const int* in_sizes, int n_in,
                              void* d_out, int out_size)
{
    const float* in  = (const float*)d_in[0];
    const float* tbx = (const float*)d_in[1];
    const int*   tcl = (const int*)d_in[2];
    float* out = (float*)d_out;

    dim3 grid(BSZ*NA, NBY);
    yolo_fused<<<grid, CPB>>>(in, tbx, tcl, out);
}